// round 1
// baseline (speedup 1.0000x reference)
#include <cuda_runtime.h>
#include <cuda_bf16.h>
#include <math_constants.h>

// Problem constants
#define B_  2
#define S_  2048
#define H_  1024
#define NH_ 16
#define HD_ 64
#define MROWS_ (B_ * S_)          // 4096
#define LN_ROWS_ (B_ * S_ * NH_)  // 65536

// Scratch (device globals — allocation-free rule)
__device__ float g_qkv[(size_t)MROWS_ * 3 * H_];  // [4096, 3072]
__device__ float g_qh [(size_t)MROWS_ * H_];      // [B*NH, S, HD]
__device__ float g_kh [(size_t)MROWS_ * H_];
__device__ float g_vh [(size_t)MROWS_ * H_];
__device__ float g_ctx[(size_t)MROWS_ * H_];      // [B, S, H]

// ---------------------------------------------------------------------------
// SGEMM: C[M,N] = A[M,K] @ B[K,N] + bias[N]   (all row-major, dims % 128 == 0)
// 128x128 block tile, BK=16, 256 threads, 8x8 microtile.
// ---------------------------------------------------------------------------
#define BM 128
#define BN 128
#define BK 16
#define TM 8
#define TN 8

__global__ __launch_bounds__(256) void sgemm_bias(
    const float* __restrict__ A, const float* __restrict__ Bm,
    const float* __restrict__ bias, float* __restrict__ C,
    int M, int N, int K)
{
    __shared__ float As[BK][BM];
    __shared__ float Bs[BK][BN];

    const int tid = threadIdx.x;
    const int tx = tid & 15;
    const int ty = tid >> 4;
    const int brow = blockIdx.y * BM;
    const int bcol = blockIdx.x * BN;

    float acc[TM][TN];
#pragma unroll
    for (int i = 0; i < TM; i++)
#pragma unroll
        for (int j = 0; j < TN; j++) acc[i][j] = 0.f;

    const int aRow  = tid >> 2;        // 0..63
    const int aCol4 = (tid & 3) * 4;   // 0,4,8,12
    const int bRow  = tid >> 5;        // 0..7
    const int bCol4 = (tid & 31) * 4;  // 0..124

    for (int k0 = 0; k0 < K; k0 += BK) {
#pragma unroll
        for (int r = 0; r < 2; r++) {
            int row = aRow + r * 64;
            float4 v = *(const float4*)&A[(size_t)(brow + row) * K + k0 + aCol4];
            As[aCol4 + 0][row] = v.x;
            As[aCol4 + 1][row] = v.y;
            As[aCol4 + 2][row] = v.z;
            As[aCol4 + 3][row] = v.w;
        }
#pragma unroll
        for (int r = 0; r < 2; r++) {
            int krow = bRow + r * 8;
            float4 v = *(const float4*)&Bm[(size_t)(k0 + krow) * N + bcol + bCol4];
            *(float4*)&Bs[krow][bCol4] = v;
        }
        __syncthreads();

#pragma unroll
        for (int kk = 0; kk < BK; kk++) {
            float af[TM], bf[TN];
#pragma unroll
            for (int i = 0; i < TM; i++) af[i] = As[kk][ty * TM + i];
#pragma unroll
            for (int j = 0; j < TN; j++) bf[j] = Bs[kk][tx * TN + j];
#pragma unroll
            for (int i = 0; i < TM; i++)
#pragma unroll
                for (int j = 0; j < TN; j++)
                    acc[i][j] = fmaf(af[i], bf[j], acc[i][j]);
        }
        __syncthreads();
    }

#pragma unroll
    for (int i = 0; i < TM; i++) {
        int row = brow + ty * TM + i;
#pragma unroll
        for (int j = 0; j < TN; j += 4) {
            int col = bcol + tx * TN + j;
            float4 o;
            o.x = acc[i][j + 0] + bias[col + 0];
            o.y = acc[i][j + 1] + bias[col + 1];
            o.z = acc[i][j + 2] + bias[col + 2];
            o.w = acc[i][j + 3] + bias[col + 3];
            *(float4*)&C[(size_t)row * N + col] = o;
        }
    }
}

// ---------------------------------------------------------------------------
// Split QKV + per-head LayerNorm on Q,K (HD=64), plain copy for V.
// One warp per (type, b, s, head) row. Output head-major [B*NH, S, HD].
// ---------------------------------------------------------------------------
__global__ __launch_bounds__(256) void qkv_split_ln(
    const float* __restrict__ qkv,
    const float* __restrict__ qg, const float* __restrict__ qb,
    const float* __restrict__ kg, const float* __restrict__ kb,
    float* __restrict__ qh, float* __restrict__ kh, float* __restrict__ vh)
{
    int w = (blockIdx.x * blockDim.x + threadIdx.x) >> 5;
    int lane = threadIdx.x & 31;
    int t = w / LN_ROWS_;      // 0:q 1:k 2:v
    int row = w - t * LN_ROWS_;
    if (t >= 3) return;

    int b = row / (S_ * NH_);
    int rem = row - b * (S_ * NH_);
    int s = rem / NH_;
    int n = rem - s * NH_;

    const float* src = qkv + (size_t)(b * S_ + s) * (3 * H_) + t * H_ + n * HD_;
    float* dst = (t == 0 ? qh : (t == 1 ? kh : vh)) +
                 ((size_t)(b * NH_ + n) * S_ + s) * HD_;

    float x0 = src[lane];
    float x1 = src[lane + 32];
    if (t == 2) { dst[lane] = x0; dst[lane + 32] = x1; return; }

    float s1 = x0 + x1;
    float s2 = x0 * x0 + x1 * x1;
#pragma unroll
    for (int o = 16; o > 0; o >>= 1) {
        s1 += __shfl_xor_sync(0xffffffffu, s1, o);
        s2 += __shfl_xor_sync(0xffffffffu, s2, o);
    }
    float mu  = s1 * (1.0f / HD_);
    float var = s2 * (1.0f / HD_) - mu * mu;
    float inv = rsqrtf(var + 1e-5f);

    const float* g  = (t == 0) ? qg : kg;
    const float* be = (t == 0) ? qb : kb;
    dst[lane]      = (x0 - mu) * inv * g[lane]      + be[lane];
    dst[lane + 32] = (x1 - mu) * inv * g[lane + 32] + be[lane + 32];
}

// ---------------------------------------------------------------------------
// Causal flash attention, fp32. Block = (bh, q-tile of 64 rows).
// K tiles of 32 keys. 256 threads: tx=tid&15 (cols), ty=tid>>4 (rows).
// Scores microtile 4x2 per thread; O microtile 4x4.
// ---------------------------------------------------------------------------
__global__ __launch_bounds__(256) void flash_attn(
    const float* __restrict__ qh, const float* __restrict__ kh,
    const float* __restrict__ vh, float* __restrict__ ctx)
{
    __shared__ float Qs[64][65];
    __shared__ float Ks[32][65];
    __shared__ float Vs[32][65];
    __shared__ float Ps[64][33];
    __shared__ float red[64][17];
    __shared__ float mrow[64], lrow[64];

    const int bh = blockIdx.y;   // 0..31
    const int qt = blockIdx.x;   // 0..31
    const int tid = threadIdx.x;
    const int tx = tid & 15;
    const int ty = tid >> 4;

    const float* Q  = qh + (size_t)bh * S_ * HD_ + (size_t)qt * 64 * HD_;
    const float* Kp = kh + (size_t)bh * S_ * HD_;
    const float* Vp = vh + (size_t)bh * S_ * HD_;

    // Load Q tile 64x64
    for (int i = tid; i < 64 * 16; i += 256) {
        int r = i >> 4, c4 = (i & 15) * 4;
        float4 v = *(const float4*)&Q[r * HD_ + c4];
        Qs[r][c4 + 0] = v.x; Qs[r][c4 + 1] = v.y;
        Qs[r][c4 + 2] = v.z; Qs[r][c4 + 3] = v.w;
    }
    if (tid < 64) { mrow[tid] = -CUDART_INF_F; lrow[tid] = 0.f; }

    float o[4][4];
#pragma unroll
    for (int i = 0; i < 4; i++)
#pragma unroll
        for (int j = 0; j < 4; j++) o[i][j] = 0.f;

    __syncthreads();

    const int nkt = (qt + 1) * 2;          // 32-key tiles up to causal bound
    const float scale = 0.125f;            // 1/sqrt(64)
    const int qbase = qt * 64;

    for (int kt = 0; kt < nkt; kt++) {
        // Load K,V tiles (32x64 each)
        for (int i = tid; i < 32 * 16; i += 256) {
            int r = i >> 4, c4 = (i & 15) * 4;
            float4 kv = *(const float4*)&Kp[(size_t)(kt * 32 + r) * HD_ + c4];
            Ks[r][c4 + 0] = kv.x; Ks[r][c4 + 1] = kv.y;
            Ks[r][c4 + 2] = kv.z; Ks[r][c4 + 3] = kv.w;
            float4 vv = *(const float4*)&Vp[(size_t)(kt * 32 + r) * HD_ + c4];
            Vs[r][c4 + 0] = vv.x; Vs[r][c4 + 1] = vv.y;
            Vs[r][c4 + 2] = vv.z; Vs[r][c4 + 3] = vv.w;
        }
        __syncthreads();  // (1) tiles ready

        // S = Q @ K^T  (4x2 per thread)
        float s[4][2];
#pragma unroll
        for (int i = 0; i < 4; i++) { s[i][0] = 0.f; s[i][1] = 0.f; }
#pragma unroll
        for (int d = 0; d < 64; d++) {
            float q0 = Qs[ty * 4 + 0][d];
            float q1 = Qs[ty * 4 + 1][d];
            float q2 = Qs[ty * 4 + 2][d];
            float q3 = Qs[ty * 4 + 3][d];
            float k0 = Ks[tx * 2 + 0][d];
            float k1 = Ks[tx * 2 + 1][d];
            s[0][0] = fmaf(q0, k0, s[0][0]); s[0][1] = fmaf(q0, k1, s[0][1]);
            s[1][0] = fmaf(q1, k0, s[1][0]); s[1][1] = fmaf(q1, k1, s[1][1]);
            s[2][0] = fmaf(q2, k0, s[2][0]); s[2][1] = fmaf(q2, k1, s[2][1]);
            s[3][0] = fmaf(q3, k0, s[3][0]); s[3][1] = fmaf(q3, k1, s[3][1]);
        }

        // scale + causal mask
        const int kbase = kt * 32;
#pragma unroll
        for (int i = 0; i < 4; i++) {
            int qi = qbase + ty * 4 + i;
#pragma unroll
            for (int j = 0; j < 2; j++) {
                int kj = kbase + tx * 2 + j;
                s[i][j] = (kj <= qi) ? s[i][j] * scale : -CUDART_INF_F;
            }
        }

        // partial row max
#pragma unroll
        for (int i = 0; i < 4; i++)
            red[ty * 4 + i][tx] = fmaxf(s[i][0], s[i][1]);
        __syncthreads();  // (2) maxes ready

        float mnew[4], alpha[4], p[4][2], psum[4];
#pragma unroll
        for (int i = 0; i < 4; i++) {
            int r = ty * 4 + i;
            float m = red[r][0];
#pragma unroll
            for (int x = 1; x < 16; x++) m = fmaxf(m, red[r][x]);
            float mo = mrow[r];
            mnew[i]  = fmaxf(mo, m);
            alpha[i] = __expf(mo - mnew[i]);
            psum[i]  = 0.f;
#pragma unroll
            for (int j = 0; j < 2; j++) {
                p[i][j] = __expf(s[i][j] - mnew[i]);
                psum[i] += p[i][j];
            }
        }
        __syncthreads();  // (3) done reading red(max) and mrow

        // partial row sums + P to smem
#pragma unroll
        for (int i = 0; i < 4; i++) {
            red[ty * 4 + i][tx] = psum[i];
            Ps[ty * 4 + i][tx * 2 + 0] = p[i][0];
            Ps[ty * 4 + i][tx * 2 + 1] = p[i][1];
        }
        __syncthreads();  // (4) sums + P ready

        // O rescale + PV accumulate
#pragma unroll
        for (int i = 0; i < 4; i++) {
            float a = alpha[i];
            o[i][0] *= a; o[i][1] *= a; o[i][2] *= a; o[i][3] *= a;
        }
#pragma unroll
        for (int k = 0; k < 32; k++) {
            float v0 = Vs[k][tx * 4 + 0];
            float v1 = Vs[k][tx * 4 + 1];
            float v2 = Vs[k][tx * 4 + 2];
            float v3 = Vs[k][tx * 4 + 3];
#pragma unroll
            for (int i = 0; i < 4; i++) {
                float pr = Ps[ty * 4 + i][k];
                o[i][0] = fmaf(pr, v0, o[i][0]);
                o[i][1] = fmaf(pr, v1, o[i][1]);
                o[i][2] = fmaf(pr, v2, o[i][2]);
                o[i][3] = fmaf(pr, v3, o[i][3]);
            }
        }

        // update stats (tx==0 writes; value identical across tx)
        if (tx == 0) {
#pragma unroll
            for (int i = 0; i < 4; i++) {
                int r = ty * 4 + i;
                float lsum = 0.f;
#pragma unroll
                for (int x = 0; x < 16; x++) lsum += red[r][x];
                lrow[r] = lrow[r] * alpha[i] + lsum;
                mrow[r] = mnew[i];
            }
        }
        __syncthreads();  // (5) stats stored; Vs/Ps free for next tile
    }

    // normalize + write to ctx in [B,S,H] layout
    const int b = bh / NH_;
    const int n = bh - b * NH_;
#pragma unroll
    for (int i = 0; i < 4; i++) {
        int r = ty * 4 + i;
        int srow = qbase + r;
        float inv = 1.0f / lrow[r];
        float4 ov;
        ov.x = o[i][0] * inv; ov.y = o[i][1] * inv;
        ov.z = o[i][2] * inv; ov.w = o[i][3] * inv;
        *(float4*)&ctx[(size_t)(b * S_ + srow) * H_ + n * HD_ + tx * 4] = ov;
    }
}

// ---------------------------------------------------------------------------
extern "C" void kernel_launch(void* const* d_in, const int* in_sizes, int n_in,
                              void* d_out, int out_size)
{
    const float* hs = (const float*)d_in[0];
    const float* Wa = (const float*)d_in[1];
    const float* ba = (const float*)d_in[2];
    const float* Wp = (const float*)d_in[3];
    const float* bp = (const float*)d_in[4];
    const float* qg = (const float*)d_in[5];
    const float* qb = (const float*)d_in[6];
    const float* kg = (const float*)d_in[7];
    const float* kb = (const float*)d_in[8];
    float* out = (float*)d_out;

    float *qkv, *qh, *kh, *vh, *ctx;
    cudaGetSymbolAddress((void**)&qkv, g_qkv);
    cudaGetSymbolAddress((void**)&qh,  g_qh);
    cudaGetSymbolAddress((void**)&kh,  g_kh);
    cudaGetSymbolAddress((void**)&vh,  g_vh);
    cudaGetSymbolAddress((void**)&ctx, g_ctx);

    // 1) QKV GEMM: [4096,1024] @ [1024,3072] + bias
    sgemm_bias<<<dim3(3 * H_ / BN, MROWS_ / BM), 256>>>(hs, Wa, ba, qkv,
                                                        MROWS_, 3 * H_, H_);

    // 2) split + QK layernorm  (3*65536 warps)
    {
        int warps = 3 * LN_ROWS_;
        int blocks = (warps * 32 + 255) / 256;
        qkv_split_ln<<<blocks, 256>>>(qkv, qg, qb, kg, kb, qh, kh, vh);
    }

    // 3) causal flash attention
    flash_attn<<<dim3(S_ / 64, B_ * NH_), 256>>>(qh, kh, vh, ctx);

    // 4) output projection: [4096,1024] @ [1024,1024] + bias
    sgemm_bias<<<dim3(H_ / BN, MROWS_ / BM), 256>>>(ctx, Wp, bp, out,
                                                    MROWS_, H_, H_);
}

// round 2
// speedup vs baseline: 1.2652x; 1.2652x over previous
#include <cuda_runtime.h>
#include <cuda_bf16.h>
#include <math_constants.h>
#include <cstdint>

// Problem constants
#define B_  2
#define S_  2048
#define H_  1024
#define NH_ 16
#define HD_ 64
#define MROWS_ (B_ * S_)          // 4096
#define LN_ROWS_ (B_ * S_ * NH_)  // 65536

// Scratch (device globals — allocation-free rule)
__device__ float g_qkv[(size_t)MROWS_ * 3 * H_];  // [4096, 3072]
__device__ float g_qh [(size_t)MROWS_ * H_];      // [B*NH, S, HD]
__device__ float g_kh [(size_t)MROWS_ * H_];
__device__ float g_vh [(size_t)MROWS_ * H_];
__device__ float g_ctx[(size_t)MROWS_ * H_];      // [B, S, H]

// ---------------------------------------------------------------------------
// tf32 helpers
// ---------------------------------------------------------------------------
__device__ __forceinline__ float tf32r(float x) {
    float y;
    asm("cvt.rna.tf32.f32 %0, %1;" : "=f"(y) : "f"(x));
    return y;
}

__device__ __forceinline__ void mma_tf32(float c[4], const uint32_t a[4],
                                         const uint32_t b[2]) {
    asm volatile(
        "mma.sync.aligned.m16n8k8.row.col.f32.tf32.tf32.f32 "
        "{%0,%1,%2,%3}, {%4,%5,%6,%7}, {%8,%9}, {%0,%1,%2,%3};"
        : "+f"(c[0]), "+f"(c[1]), "+f"(c[2]), "+f"(c[3])
        : "r"(a[0]), "r"(a[1]), "r"(a[2]), "r"(a[3]), "r"(b[0]), "r"(b[1]));
}

// ---------------------------------------------------------------------------
// TF32 tensor-core GEMM: C[M,N] = A[M,K] @ B[K,N] + bias[N]
// 128x128 block tile, BK=16 double-buffered. 8 warps, each 64x32 warp tile
// built from 4x4 m16n8k8 MMAs. One __syncthreads per mainloop iteration.
// ---------------------------------------------------------------------------
__global__ __launch_bounds__(256, 2) void gemm_tf32(
    const float* __restrict__ A, const float* __restrict__ Bm,
    const float* __restrict__ bias, float* __restrict__ C,
    int M, int N, int K)
{
    __shared__ float As[2][16][130];  // [buf][k][m]  (stride 130: conflict-aware)
    __shared__ float Bs[2][16][132];  // [buf][k][n]

    const int tid  = threadIdx.x;
    const int lane = tid & 31;
    const int warp = tid >> 5;
    const int wm = (warp & 1) * 64;   // warp row offset in tile
    const int wn = (warp >> 1) * 32;  // warp col offset in tile
    const int gid = lane >> 2;        // 0..7
    const int tig = lane & 3;         // 0..3
    const int brow = blockIdx.y * 128;
    const int bcol = blockIdx.x * 128;

    const int aRow = tid >> 2;        // 0..63 (+64 for second row)
    const int aCol = (tid & 3) * 4;   // 0,4,8,12
    const int bRow = tid >> 5;        // 0..7 (+8)
    const int bCol = (tid & 31) * 4;  // 0..124

    const float* Aptr  = A + (size_t)(brow + aRow) * K + aCol;
    const float* Aptr2 = Aptr + (size_t)64 * K;
    const float* Bptr  = Bm + (size_t)bRow * N + bcol + bCol;
    const float* Bptr2 = Bptr + (size_t)8 * N;

    float c[4][4][4];
#pragma unroll
    for (int i = 0; i < 4; i++)
#pragma unroll
        for (int j = 0; j < 4; j++)
#pragma unroll
            for (int r = 0; r < 4; r++) c[i][j][r] = 0.f;

    float4 av0, av1, bv0, bv1;

    // prologue: load + store tile 0
    av0 = *(const float4*)(Aptr);
    av1 = *(const float4*)(Aptr2);
    bv0 = *(const float4*)(Bptr);
    bv1 = *(const float4*)(Bptr2);
    {
        As[0][aCol + 0][aRow] = tf32r(av0.x);
        As[0][aCol + 1][aRow] = tf32r(av0.y);
        As[0][aCol + 2][aRow] = tf32r(av0.z);
        As[0][aCol + 3][aRow] = tf32r(av0.w);
        As[0][aCol + 0][aRow + 64] = tf32r(av1.x);
        As[0][aCol + 1][aRow + 64] = tf32r(av1.y);
        As[0][aCol + 2][aRow + 64] = tf32r(av1.z);
        As[0][aCol + 3][aRow + 64] = tf32r(av1.w);
        float4 t0 = make_float4(tf32r(bv0.x), tf32r(bv0.y), tf32r(bv0.z), tf32r(bv0.w));
        float4 t1 = make_float4(tf32r(bv1.x), tf32r(bv1.y), tf32r(bv1.z), tf32r(bv1.w));
        *(float4*)&Bs[0][bRow][bCol]     = t0;
        *(float4*)&Bs[0][bRow + 8][bCol] = t1;
    }
    __syncthreads();

    const int iters = K / 16;
    for (int t = 0; t < iters; t++) {
        const int buf = t & 1;
        if (t + 1 < iters) {
            const int k0 = (t + 1) * 16;
            av0 = *(const float4*)(Aptr + k0);
            av1 = *(const float4*)(Aptr2 + k0);
            bv0 = *(const float4*)(Bptr + (size_t)k0 * N);
            bv1 = *(const float4*)(Bptr2 + (size_t)k0 * N);
        }

#pragma unroll
        for (int ks = 0; ks < 2; ks++) {
            const int k0 = ks * 8;
            uint32_t af[4][4], bf[4][2];
#pragma unroll
            for (int mt = 0; mt < 4; mt++) {
                const int r = wm + mt * 16 + gid;
                af[mt][0] = __float_as_uint(As[buf][k0 + tig][r]);
                af[mt][1] = __float_as_uint(As[buf][k0 + tig][r + 8]);
                af[mt][2] = __float_as_uint(As[buf][k0 + tig + 4][r]);
                af[mt][3] = __float_as_uint(As[buf][k0 + tig + 4][r + 8]);
            }
#pragma unroll
            for (int nt = 0; nt < 4; nt++) {
                const int ncol = wn + nt * 8 + gid;
                bf[nt][0] = __float_as_uint(Bs[buf][k0 + tig][ncol]);
                bf[nt][1] = __float_as_uint(Bs[buf][k0 + tig + 4][ncol]);
            }
#pragma unroll
            for (int mt = 0; mt < 4; mt++)
#pragma unroll
                for (int nt = 0; nt < 4; nt++)
                    mma_tf32(c[mt][nt], af[mt], bf[nt]);
        }

        if (t + 1 < iters) {
            const int nb = (t + 1) & 1;
            As[nb][aCol + 0][aRow] = tf32r(av0.x);
            As[nb][aCol + 1][aRow] = tf32r(av0.y);
            As[nb][aCol + 2][aRow] = tf32r(av0.z);
            As[nb][aCol + 3][aRow] = tf32r(av0.w);
            As[nb][aCol + 0][aRow + 64] = tf32r(av1.x);
            As[nb][aCol + 1][aRow + 64] = tf32r(av1.y);
            As[nb][aCol + 2][aRow + 64] = tf32r(av1.z);
            As[nb][aCol + 3][aRow + 64] = tf32r(av1.w);
            float4 t0 = make_float4(tf32r(bv0.x), tf32r(bv0.y), tf32r(bv0.z), tf32r(bv0.w));
            float4 t1 = make_float4(tf32r(bv1.x), tf32r(bv1.y), tf32r(bv1.z), tf32r(bv1.w));
            *(float4*)&Bs[nb][bRow][bCol]     = t0;
            *(float4*)&Bs[nb][bRow + 8][bCol] = t1;
            __syncthreads();
        }
    }

    // epilogue: bias add + store
#pragma unroll
    for (int mt = 0; mt < 4; mt++) {
        const int row = brow + wm + mt * 16 + gid;
#pragma unroll
        for (int nt = 0; nt < 4; nt++) {
            const int col = bcol + wn + nt * 8 + tig * 2;
            const float b0 = bias[col], b1 = bias[col + 1];
            float2 o0 = make_float2(c[mt][nt][0] + b0, c[mt][nt][1] + b1);
            float2 o1 = make_float2(c[mt][nt][2] + b0, c[mt][nt][3] + b1);
            *(float2*)&C[(size_t)row * N + col]       = o0;
            *(float2*)&C[(size_t)(row + 8) * N + col] = o1;
        }
    }
}

// ---------------------------------------------------------------------------
// Split QKV + per-head LayerNorm on Q,K (HD=64), plain copy for V.
// One warp per (type, b, s, head) row. Output head-major [B*NH, S, HD].
// ---------------------------------------------------------------------------
__global__ __launch_bounds__(256) void qkv_split_ln(
    const float* __restrict__ qkv,
    const float* __restrict__ qg, const float* __restrict__ qb,
    const float* __restrict__ kg, const float* __restrict__ kb,
    float* __restrict__ qh, float* __restrict__ kh, float* __restrict__ vh)
{
    int w = (blockIdx.x * blockDim.x + threadIdx.x) >> 5;
    int lane = threadIdx.x & 31;
    int t = w / LN_ROWS_;      // 0:q 1:k 2:v
    int row = w - t * LN_ROWS_;
    if (t >= 3) return;

    int b = row / (S_ * NH_);
    int rem = row - b * (S_ * NH_);
    int s = rem / NH_;
    int n = rem - s * NH_;

    const float* src = qkv + (size_t)(b * S_ + s) * (3 * H_) + t * H_ + n * HD_;
    float* dst = (t == 0 ? qh : (t == 1 ? kh : vh)) +
                 ((size_t)(b * NH_ + n) * S_ + s) * HD_;

    float x0 = src[lane];
    float x1 = src[lane + 32];
    if (t == 2) { dst[lane] = x0; dst[lane + 32] = x1; return; }

    float s1 = x0 + x1;
    float s2 = x0 * x0 + x1 * x1;
#pragma unroll
    for (int o = 16; o > 0; o >>= 1) {
        s1 += __shfl_xor_sync(0xffffffffu, s1, o);
        s2 += __shfl_xor_sync(0xffffffffu, s2, o);
    }
    float mu  = s1 * (1.0f / HD_);
    float var = s2 * (1.0f / HD_) - mu * mu;
    float inv = rsqrtf(var + 1e-5f);

    const float* g  = (t == 0) ? qg : kg;
    const float* be = (t == 0) ? qb : kb;
    dst[lane]      = (x0 - mu) * inv * g[lane]      + be[lane];
    dst[lane + 32] = (x1 - mu) * inv * g[lane + 32] + be[lane + 32];
}

// ---------------------------------------------------------------------------
// Causal flash attention, fp32. Block = (bh, q-tile of 64 rows).
// K tiles of 32 keys. 256 threads: tx=tid&15 (cols), ty=tid>>4 (rows).
// ---------------------------------------------------------------------------
__global__ __launch_bounds__(256) void flash_attn(
    const float* __restrict__ qh, const float* __restrict__ kh,
    const float* __restrict__ vh, float* __restrict__ ctx)
{
    __shared__ float Qs[64][65];
    __shared__ float Ks[32][65];
    __shared__ float Vs[32][65];
    __shared__ float Ps[64][33];
    __shared__ float red[64][17];
    __shared__ float mrow[64], lrow[64];

    const int bh = blockIdx.y;   // 0..31
    const int qt = blockIdx.x;   // 0..31
    const int tid = threadIdx.x;
    const int tx = tid & 15;
    const int ty = tid >> 4;

    const float* Q  = qh + (size_t)bh * S_ * HD_ + (size_t)qt * 64 * HD_;
    const float* Kp = kh + (size_t)bh * S_ * HD_;
    const float* Vp = vh + (size_t)bh * S_ * HD_;

    for (int i = tid; i < 64 * 16; i += 256) {
        int r = i >> 4, c4 = (i & 15) * 4;
        float4 v = *(const float4*)&Q[r * HD_ + c4];
        Qs[r][c4 + 0] = v.x; Qs[r][c4 + 1] = v.y;
        Qs[r][c4 + 2] = v.z; Qs[r][c4 + 3] = v.w;
    }
    if (tid < 64) { mrow[tid] = -CUDART_INF_F; lrow[tid] = 0.f; }

    float o[4][4];
#pragma unroll
    for (int i = 0; i < 4; i++)
#pragma unroll
        for (int j = 0; j < 4; j++) o[i][j] = 0.f;

    __syncthreads();

    const int nkt = (qt + 1) * 2;
    const float scale = 0.125f;
    const int qbase = qt * 64;

    for (int kt = 0; kt < nkt; kt++) {
        for (int i = tid; i < 32 * 16; i += 256) {
            int r = i >> 4, c4 = (i & 15) * 4;
            float4 kv = *(const float4*)&Kp[(size_t)(kt * 32 + r) * HD_ + c4];
            Ks[r][c4 + 0] = kv.x; Ks[r][c4 + 1] = kv.y;
            Ks[r][c4 + 2] = kv.z; Ks[r][c4 + 3] = kv.w;
            float4 vv = *(const float4*)&Vp[(size_t)(kt * 32 + r) * HD_ + c4];
            Vs[r][c4 + 0] = vv.x; Vs[r][c4 + 1] = vv.y;
            Vs[r][c4 + 2] = vv.z; Vs[r][c4 + 3] = vv.w;
        }
        __syncthreads();

        float s[4][2];
#pragma unroll
        for (int i = 0; i < 4; i++) { s[i][0] = 0.f; s[i][1] = 0.f; }
#pragma unroll
        for (int d = 0; d < 64; d++) {
            float q0 = Qs[ty * 4 + 0][d];
            float q1 = Qs[ty * 4 + 1][d];
            float q2 = Qs[ty * 4 + 2][d];
            float q3 = Qs[ty * 4 + 3][d];
            float k0 = Ks[tx * 2 + 0][d];
            float k1 = Ks[tx * 2 + 1][d];
            s[0][0] = fmaf(q0, k0, s[0][0]); s[0][1] = fmaf(q0, k1, s[0][1]);
            s[1][0] = fmaf(q1, k0, s[1][0]); s[1][1] = fmaf(q1, k1, s[1][1]);
            s[2][0] = fmaf(q2, k0, s[2][0]); s[2][1] = fmaf(q2, k1, s[2][1]);
            s[3][0] = fmaf(q3, k0, s[3][0]); s[3][1] = fmaf(q3, k1, s[3][1]);
        }

        const int kbase = kt * 32;
#pragma unroll
        for (int i = 0; i < 4; i++) {
            int qi = qbase + ty * 4 + i;
#pragma unroll
            for (int j = 0; j < 2; j++) {
                int kj = kbase + tx * 2 + j;
                s[i][j] = (kj <= qi) ? s[i][j] * scale : -CUDART_INF_F;
            }
        }

#pragma unroll
        for (int i = 0; i < 4; i++)
            red[ty * 4 + i][tx] = fmaxf(s[i][0], s[i][1]);
        __syncthreads();

        float mnew[4], alpha[4], p[4][2], psum[4];
#pragma unroll
        for (int i = 0; i < 4; i++) {
            int r = ty * 4 + i;
            float m = red[r][0];
#pragma unroll
            for (int x = 1; x < 16; x++) m = fmaxf(m, red[r][x]);
            float mo = mrow[r];
            mnew[i]  = fmaxf(mo, m);
            alpha[i] = __expf(mo - mnew[i]);
            psum[i]  = 0.f;
#pragma unroll
            for (int j = 0; j < 2; j++) {
                p[i][j] = __expf(s[i][j] - mnew[i]);
                psum[i] += p[i][j];
            }
        }
        __syncthreads();

#pragma unroll
        for (int i = 0; i < 4; i++) {
            red[ty * 4 + i][tx] = psum[i];
            Ps[ty * 4 + i][tx * 2 + 0] = p[i][0];
            Ps[ty * 4 + i][tx * 2 + 1] = p[i][1];
        }
        __syncthreads();

#pragma unroll
        for (int i = 0; i < 4; i++) {
            float a = alpha[i];
            o[i][0] *= a; o[i][1] *= a; o[i][2] *= a; o[i][3] *= a;
        }
#pragma unroll
        for (int k = 0; k < 32; k++) {
            float v0 = Vs[k][tx * 4 + 0];
            float v1 = Vs[k][tx * 4 + 1];
            float v2 = Vs[k][tx * 4 + 2];
            float v3 = Vs[k][tx * 4 + 3];
#pragma unroll
            for (int i = 0; i < 4; i++) {
                float pr = Ps[ty * 4 + i][k];
                o[i][0] = fmaf(pr, v0, o[i][0]);
                o[i][1] = fmaf(pr, v1, o[i][1]);
                o[i][2] = fmaf(pr, v2, o[i][2]);
                o[i][3] = fmaf(pr, v3, o[i][3]);
            }
        }

        if (tx == 0) {
#pragma unroll
            for (int i = 0; i < 4; i++) {
                int r = ty * 4 + i;
                float lsum = 0.f;
#pragma unroll
                for (int x = 0; x < 16; x++) lsum += red[r][x];
                lrow[r] = lrow[r] * alpha[i] + lsum;
                mrow[r] = mnew[i];
            }
        }
        __syncthreads();
    }

    const int b = bh / NH_;
    const int n = bh - b * NH_;
#pragma unroll
    for (int i = 0; i < 4; i++) {
        int r = ty * 4 + i;
        int srow = qbase + r;
        float inv = 1.0f / lrow[r];
        float4 ov;
        ov.x = o[i][0] * inv; ov.y = o[i][1] * inv;
        ov.z = o[i][2] * inv; ov.w = o[i][3] * inv;
        *(float4*)&ctx[(size_t)(b * S_ + srow) * H_ + n * HD_ + tx * 4] = ov;
    }
}

// ---------------------------------------------------------------------------
extern "C" void kernel_launch(void* const* d_in, const int* in_sizes, int n_in,
                              void* d_out, int out_size)
{
    const float* hs = (const float*)d_in[0];
    const float* Wa = (const float*)d_in[1];
    const float* ba = (const float*)d_in[2];
    const float* Wp = (const float*)d_in[3];
    const float* bp = (const float*)d_in[4];
    const float* qg = (const float*)d_in[5];
    const float* qb = (const float*)d_in[6];
    const float* kg = (const float*)d_in[7];
    const float* kb = (const float*)d_in[8];
    float* out = (float*)d_out;

    float *qkv, *qh, *kh, *vh, *ctx;
    cudaGetSymbolAddress((void**)&qkv, g_qkv);
    cudaGetSymbolAddress((void**)&qh,  g_qh);
    cudaGetSymbolAddress((void**)&kh,  g_kh);
    cudaGetSymbolAddress((void**)&vh,  g_vh);
    cudaGetSymbolAddress((void**)&ctx, g_ctx);

    // 1) QKV GEMM: [4096,1024] @ [1024,3072] + bias (tf32 tensor cores)
    gemm_tf32<<<dim3(3 * H_ / 128, MROWS_ / 128), 256>>>(hs, Wa, ba, qkv,
                                                         MROWS_, 3 * H_, H_);

    // 2) split + QK layernorm
    {
        int warps = 3 * LN_ROWS_;
        int blocks = (warps * 32 + 255) / 256;
        qkv_split_ln<<<blocks, 256>>>(qkv, qg, qb, kg, kb, qh, kh, vh);
    }

    // 3) causal flash attention
    flash_attn<<<dim3(S_ / 64, B_ * NH_), 256>>>(qh, kh, vh, ctx);

    // 4) output projection: [4096,1024] @ [1024,1024] + bias
    gemm_tf32<<<dim3(H_ / 128, MROWS_ / 128), 256>>>(ctx, Wp, bp, out,
                                                     MROWS_, H_, H_);
}

// round 3
// speedup vs baseline: 2.1437x; 1.6943x over previous
#include <cuda_runtime.h>
#include <cuda_bf16.h>
#include <math_constants.h>
#include <cstdint>

// Problem constants
#define B_  2
#define S_  2048
#define H_  1024
#define NH_ 16
#define HD_ 64
#define MROWS_ (B_ * S_)          // 4096
#define LN_ROWS_ (B_ * S_ * NH_)  // 65536

// Scratch (device globals — allocation-free rule)
__device__ float g_qkv[(size_t)MROWS_ * 3 * H_];  // [4096, 3072]
__device__ float g_qh [(size_t)MROWS_ * H_];      // [B*NH, S, HD]
__device__ float g_kh [(size_t)MROWS_ * H_];
__device__ float g_vh [(size_t)MROWS_ * H_];
__device__ float g_ctx[(size_t)MROWS_ * H_];      // [B, S, H]

// ---------------------------------------------------------------------------
// tf32 helpers
// ---------------------------------------------------------------------------
__device__ __forceinline__ float tf32r(float x) {
    float y;
    asm("cvt.rna.tf32.f32 %0, %1;" : "=f"(y) : "f"(x));
    return y;
}

__device__ __forceinline__ void mma_tf32(float c[4], const uint32_t a[4],
                                         const uint32_t b[2]) {
    asm volatile(
        "mma.sync.aligned.m16n8k8.row.col.f32.tf32.tf32.f32 "
        "{%0,%1,%2,%3}, {%4,%5,%6,%7}, {%8,%9}, {%0,%1,%2,%3};"
        : "+f"(c[0]), "+f"(c[1]), "+f"(c[2]), "+f"(c[3])
        : "r"(a[0]), "r"(a[1]), "r"(a[2]), "r"(a[3]), "r"(b[0]), "r"(b[1]));
}

// ---------------------------------------------------------------------------
// TF32 tensor-core GEMM: C[M,N] = A[M,K] @ B[K,N] + bias[N]
// ---------------------------------------------------------------------------
__global__ __launch_bounds__(256, 2) void gemm_tf32(
    const float* __restrict__ A, const float* __restrict__ Bm,
    const float* __restrict__ bias, float* __restrict__ C,
    int M, int N, int K)
{
    __shared__ float As[2][16][130];
    __shared__ float Bs[2][16][132];

    const int tid  = threadIdx.x;
    const int lane = tid & 31;
    const int warp = tid >> 5;
    const int wm = (warp & 1) * 64;
    const int wn = (warp >> 1) * 32;
    const int gid = lane >> 2;
    const int tig = lane & 3;
    const int brow = blockIdx.y * 128;
    const int bcol = blockIdx.x * 128;

    const int aRow = tid >> 2;
    const int aCol = (tid & 3) * 4;
    const int bRow = tid >> 5;
    const int bCol = (tid & 31) * 4;

    const float* Aptr  = A + (size_t)(brow + aRow) * K + aCol;
    const float* Aptr2 = Aptr + (size_t)64 * K;
    const float* Bptr  = Bm + (size_t)bRow * N + bcol + bCol;
    const float* Bptr2 = Bptr + (size_t)8 * N;

    float c[4][4][4];
#pragma unroll
    for (int i = 0; i < 4; i++)
#pragma unroll
        for (int j = 0; j < 4; j++)
#pragma unroll
            for (int r = 0; r < 4; r++) c[i][j][r] = 0.f;

    float4 av0, av1, bv0, bv1;

    av0 = *(const float4*)(Aptr);
    av1 = *(const float4*)(Aptr2);
    bv0 = *(const float4*)(Bptr);
    bv1 = *(const float4*)(Bptr2);
    {
        As[0][aCol + 0][aRow] = tf32r(av0.x);
        As[0][aCol + 1][aRow] = tf32r(av0.y);
        As[0][aCol + 2][aRow] = tf32r(av0.z);
        As[0][aCol + 3][aRow] = tf32r(av0.w);
        As[0][aCol + 0][aRow + 64] = tf32r(av1.x);
        As[0][aCol + 1][aRow + 64] = tf32r(av1.y);
        As[0][aCol + 2][aRow + 64] = tf32r(av1.z);
        As[0][aCol + 3][aRow + 64] = tf32r(av1.w);
        float4 t0 = make_float4(tf32r(bv0.x), tf32r(bv0.y), tf32r(bv0.z), tf32r(bv0.w));
        float4 t1 = make_float4(tf32r(bv1.x), tf32r(bv1.y), tf32r(bv1.z), tf32r(bv1.w));
        *(float4*)&Bs[0][bRow][bCol]     = t0;
        *(float4*)&Bs[0][bRow + 8][bCol] = t1;
    }
    __syncthreads();

    const int iters = K / 16;
    for (int t = 0; t < iters; t++) {
        const int buf = t & 1;
        if (t + 1 < iters) {
            const int k0 = (t + 1) * 16;
            av0 = *(const float4*)(Aptr + k0);
            av1 = *(const float4*)(Aptr2 + k0);
            bv0 = *(const float4*)(Bptr + (size_t)k0 * N);
            bv1 = *(const float4*)(Bptr2 + (size_t)k0 * N);
        }

#pragma unroll
        for (int ks = 0; ks < 2; ks++) {
            const int k0 = ks * 8;
            uint32_t af[4][4], bf[4][2];
#pragma unroll
            for (int mt = 0; mt < 4; mt++) {
                const int r = wm + mt * 16 + gid;
                af[mt][0] = __float_as_uint(As[buf][k0 + tig][r]);
                af[mt][1] = __float_as_uint(As[buf][k0 + tig][r + 8]);
                af[mt][2] = __float_as_uint(As[buf][k0 + tig + 4][r]);
                af[mt][3] = __float_as_uint(As[buf][k0 + tig + 4][r + 8]);
            }
#pragma unroll
            for (int nt = 0; nt < 4; nt++) {
                const int ncol = wn + nt * 8 + gid;
                bf[nt][0] = __float_as_uint(Bs[buf][k0 + tig][ncol]);
                bf[nt][1] = __float_as_uint(Bs[buf][k0 + tig + 4][ncol]);
            }
#pragma unroll
            for (int mt = 0; mt < 4; mt++)
#pragma unroll
                for (int nt = 0; nt < 4; nt++)
                    mma_tf32(c[mt][nt], af[mt], bf[nt]);
        }

        if (t + 1 < iters) {
            const int nb = (t + 1) & 1;
            As[nb][aCol + 0][aRow] = tf32r(av0.x);
            As[nb][aCol + 1][aRow] = tf32r(av0.y);
            As[nb][aCol + 2][aRow] = tf32r(av0.z);
            As[nb][aCol + 3][aRow] = tf32r(av0.w);
            As[nb][aCol + 0][aRow + 64] = tf32r(av1.x);
            As[nb][aCol + 1][aRow + 64] = tf32r(av1.y);
            As[nb][aCol + 2][aRow + 64] = tf32r(av1.z);
            As[nb][aCol + 3][aRow + 64] = tf32r(av1.w);
            float4 t0 = make_float4(tf32r(bv0.x), tf32r(bv0.y), tf32r(bv0.z), tf32r(bv0.w));
            float4 t1 = make_float4(tf32r(bv1.x), tf32r(bv1.y), tf32r(bv1.z), tf32r(bv1.w));
            *(float4*)&Bs[nb][bRow][bCol]     = t0;
            *(float4*)&Bs[nb][bRow + 8][bCol] = t1;
            __syncthreads();
        }
    }

#pragma unroll
    for (int mt = 0; mt < 4; mt++) {
        const int row = brow + wm + mt * 16 + gid;
#pragma unroll
        for (int nt = 0; nt < 4; nt++) {
            const int col = bcol + wn + nt * 8 + tig * 2;
            const float b0 = bias[col], b1 = bias[col + 1];
            float2 o0 = make_float2(c[mt][nt][0] + b0, c[mt][nt][1] + b1);
            float2 o1 = make_float2(c[mt][nt][2] + b0, c[mt][nt][3] + b1);
            *(float2*)&C[(size_t)row * N + col]       = o0;
            *(float2*)&C[(size_t)(row + 8) * N + col] = o1;
        }
    }
}

// ---------------------------------------------------------------------------
// Split QKV + per-head LayerNorm on Q,K (HD=64), plain copy for V.
// ---------------------------------------------------------------------------
__global__ __launch_bounds__(256) void qkv_split_ln(
    const float* __restrict__ qkv,
    const float* __restrict__ qg, const float* __restrict__ qb,
    const float* __restrict__ kg, const float* __restrict__ kb,
    float* __restrict__ qh, float* __restrict__ kh, float* __restrict__ vh)
{
    int w = (blockIdx.x * blockDim.x + threadIdx.x) >> 5;
    int lane = threadIdx.x & 31;
    int t = w / LN_ROWS_;
    int row = w - t * LN_ROWS_;
    if (t >= 3) return;

    int b = row / (S_ * NH_);
    int rem = row - b * (S_ * NH_);
    int s = rem / NH_;
    int n = rem - s * NH_;

    const float* src = qkv + (size_t)(b * S_ + s) * (3 * H_) + t * H_ + n * HD_;
    float* dst = (t == 0 ? qh : (t == 1 ? kh : vh)) +
                 ((size_t)(b * NH_ + n) * S_ + s) * HD_;

    float x0 = src[lane];
    float x1 = src[lane + 32];
    if (t == 2) { dst[lane] = x0; dst[lane + 32] = x1; return; }

    float s1 = x0 + x1;
    float s2 = x0 * x0 + x1 * x1;
#pragma unroll
    for (int o = 16; o > 0; o >>= 1) {
        s1 += __shfl_xor_sync(0xffffffffu, s1, o);
        s2 += __shfl_xor_sync(0xffffffffu, s2, o);
    }
    float mu  = s1 * (1.0f / HD_);
    float var = s2 * (1.0f / HD_) - mu * mu;
    float inv = rsqrtf(var + 1e-5f);

    const float* g  = (t == 0) ? qg : kg;
    const float* be = (t == 0) ? qb : kb;
    dst[lane]      = (x0 - mu) * inv * g[lane]      + be[lane];
    dst[lane + 32] = (x1 - mu) * inv * g[lane + 32] + be[lane + 32];
}

// ---------------------------------------------------------------------------
// Causal flash attention, TF32 tensor cores.
// CTA = 128 thr (4 warps) per 64-row Q tile; warp w owns rows [w*16, w*16+16).
// Q fragments register-resident for entire kernel. K tiles of 32 keys.
// Online softmax in registers via quad shuffles. P via per-warp smem slice.
// ---------------------------------------------------------------------------
__global__ __launch_bounds__(128, 3) void flash_attn_tc(
    const float* __restrict__ qh, const float* __restrict__ kh,
    const float* __restrict__ vh, float* __restrict__ ctx)
{
    __shared__ float Ks[32][68];   // stride 68 (mod 32 = 4): QK B-frag conflict-free
    __shared__ float Vs[32][72];   // stride 72 (mod 32 = 8): PV B-frag conflict-free
    __shared__ float Ps[64][36];   // stride 36 (mod 32 = 4); also Q staging buffer

    const int bh  = blockIdx.y;    // 0..31
    const int qt  = blockIdx.x;    // 0..31
    const int tid = threadIdx.x;
    const int lane = tid & 31;
    const int w    = tid >> 5;     // warp 0..3
    const int gid  = lane >> 2;    // 0..7
    const int tig  = lane & 3;     // 0..3
    const int qbase = qt * 64;
    const int wrow  = w * 16;

    const float* Q  = qh + (size_t)bh * S_ * HD_ + (size_t)qbase * HD_;
    const float* Kp = kh + (size_t)bh * S_ * HD_;
    const float* Vp = vh + (size_t)bh * S_ * HD_;

    // --- Load Q fragments (register-resident), staged through Ps buffer ---
    uint32_t qa[8][4];
#pragma unroll
    for (int h = 0; h < 2; h++) {
        for (int i = tid; i < 64 * 8; i += 128) {
            int r = i >> 3, c4 = (i & 7) * 4;
            float4 v = *(const float4*)&Q[r * HD_ + h * 32 + c4];
            Ps[r][c4 + 0] = tf32r(v.x);
            Ps[r][c4 + 1] = tf32r(v.y);
            Ps[r][c4 + 2] = tf32r(v.z);
            Ps[r][c4 + 3] = tf32r(v.w);
        }
        __syncthreads();
#pragma unroll
        for (int ks = 0; ks < 4; ks++) {
            qa[h * 4 + ks][0] = __float_as_uint(Ps[wrow + gid][ks * 8 + tig]);
            qa[h * 4 + ks][1] = __float_as_uint(Ps[wrow + gid + 8][ks * 8 + tig]);
            qa[h * 4 + ks][2] = __float_as_uint(Ps[wrow + gid][ks * 8 + tig + 4]);
            qa[h * 4 + ks][3] = __float_as_uint(Ps[wrow + gid + 8][ks * 8 + tig + 4]);
        }
        __syncthreads();
    }

    float o[8][4];
#pragma unroll
    for (int i = 0; i < 8; i++)
#pragma unroll
        for (int j = 0; j < 4; j++) o[i][j] = 0.f;
    float m0 = -CUDART_INF_F, m1 = -CUDART_INF_F;
    float l0 = 0.f, l1 = 0.f;

    const int r0g = qbase + wrow + gid;      // global q row for c0/c1
    const int r1g = r0g + 8;                 // global q row for c2/c3
    const int rmaxw = qbase + wrow + 15;     // max row this warp owns
    const int nkt = (qt + 1) * 2;
    const float scl = 0.125f;                // 1/sqrt(64)

    for (int kt = 0; kt < nkt; kt++) {
        const int kbase = kt * 32;
        // Load K,V tile (32x64 each), convert to tf32 at store
        for (int i = tid; i < 32 * 16; i += 128) {
            int r = i >> 4, c4 = (i & 15) * 4;
            const float* kp = &Kp[(size_t)(kbase + r) * HD_ + c4];
            float4 kv = *(const float4*)kp;
            Ks[r][c4 + 0] = tf32r(kv.x); Ks[r][c4 + 1] = tf32r(kv.y);
            Ks[r][c4 + 2] = tf32r(kv.z); Ks[r][c4 + 3] = tf32r(kv.w);
            const float* vp = &Vp[(size_t)(kbase + r) * HD_ + c4];
            float4 vv = *(const float4*)vp;
            Vs[r][c4 + 0] = tf32r(vv.x); Vs[r][c4 + 1] = tf32r(vv.y);
            Vs[r][c4 + 2] = tf32r(vv.z); Vs[r][c4 + 3] = tf32r(vv.w);
        }
        __syncthreads();

        if (kbase <= rmaxw) {   // warp-uniform: skip fully-masked tiles
            // --- S = Q @ K^T ---
            float s[4][4];
#pragma unroll
            for (int nt = 0; nt < 4; nt++)
#pragma unroll
                for (int j = 0; j < 4; j++) s[nt][j] = 0.f;
#pragma unroll
            for (int nt = 0; nt < 4; nt++) {
#pragma unroll
                for (int ks = 0; ks < 8; ks++) {
                    uint32_t b[2];
                    b[0] = __float_as_uint(Ks[nt * 8 + gid][ks * 8 + tig]);
                    b[1] = __float_as_uint(Ks[nt * 8 + gid][ks * 8 + tig + 4]);
                    mma_tf32(s[nt], qa[ks], b);
                }
            }

            // --- scale + causal mask ---
            if (kbase + 31 <= qbase + wrow) {   // tile fully valid for this warp
#pragma unroll
                for (int nt = 0; nt < 4; nt++)
#pragma unroll
                    for (int j = 0; j < 4; j++) s[nt][j] *= scl;
            } else {
#pragma unroll
                for (int nt = 0; nt < 4; nt++) {
                    int c0 = kbase + nt * 8 + tig * 2;
                    s[nt][0] = (c0     <= r0g) ? s[nt][0] * scl : -CUDART_INF_F;
                    s[nt][1] = (c0 + 1 <= r0g) ? s[nt][1] * scl : -CUDART_INF_F;
                    s[nt][2] = (c0     <= r1g) ? s[nt][2] * scl : -CUDART_INF_F;
                    s[nt][3] = (c0 + 1 <= r1g) ? s[nt][3] * scl : -CUDART_INF_F;
                }
            }

            // --- row max (quad reduce: lanes tig=0..3 share rows) ---
            float mt0 = fmaxf(fmaxf(s[0][0], s[0][1]), fmaxf(s[1][0], s[1][1]));
            mt0 = fmaxf(mt0, fmaxf(fmaxf(s[2][0], s[2][1]), fmaxf(s[3][0], s[3][1])));
            float mt1 = fmaxf(fmaxf(s[0][2], s[0][3]), fmaxf(s[1][2], s[1][3]));
            mt1 = fmaxf(mt1, fmaxf(fmaxf(s[2][2], s[2][3]), fmaxf(s[3][2], s[3][3])));
            mt0 = fmaxf(mt0, __shfl_xor_sync(0xffffffffu, mt0, 1));
            mt0 = fmaxf(mt0, __shfl_xor_sync(0xffffffffu, mt0, 2));
            mt1 = fmaxf(mt1, __shfl_xor_sync(0xffffffffu, mt1, 1));
            mt1 = fmaxf(mt1, __shfl_xor_sync(0xffffffffu, mt1, 2));

            float mn0 = fmaxf(m0, mt0), mn1 = fmaxf(m1, mt1);
            float a0 = __expf(m0 - mn0), a1 = __expf(m1 - mn1);
            m0 = mn0; m1 = mn1;

            // --- P = exp(S - m), write tf32 to per-warp Ps slice ---
            float ps0 = 0.f, ps1 = 0.f;
#pragma unroll
            for (int nt = 0; nt < 4; nt++) {
                float p0 = tf32r(__expf(s[nt][0] - mn0));
                float p1 = tf32r(__expf(s[nt][1] - mn0));
                float p2 = tf32r(__expf(s[nt][2] - mn1));
                float p3 = tf32r(__expf(s[nt][3] - mn1));
                ps0 += p0 + p1;
                ps1 += p2 + p3;
                Ps[wrow + gid][nt * 8 + tig * 2 + 0]     = p0;
                Ps[wrow + gid][nt * 8 + tig * 2 + 1]     = p1;
                Ps[wrow + gid + 8][nt * 8 + tig * 2 + 0] = p2;
                Ps[wrow + gid + 8][nt * 8 + tig * 2 + 1] = p3;
            }
            ps0 += __shfl_xor_sync(0xffffffffu, ps0, 1);
            ps0 += __shfl_xor_sync(0xffffffffu, ps0, 2);
            ps1 += __shfl_xor_sync(0xffffffffu, ps1, 1);
            ps1 += __shfl_xor_sync(0xffffffffu, ps1, 2);
            l0 = l0 * a0 + ps0;
            l1 = l1 * a1 + ps1;

            // --- rescale O ---
#pragma unroll
            for (int nt = 0; nt < 8; nt++) {
                o[nt][0] *= a0; o[nt][1] *= a0;
                o[nt][2] *= a1; o[nt][3] *= a1;
            }

            // --- O += P @ V ---
            uint32_t pa[4][4];
#pragma unroll
            for (int ks = 0; ks < 4; ks++) {
                pa[ks][0] = __float_as_uint(Ps[wrow + gid][ks * 8 + tig]);
                pa[ks][1] = __float_as_uint(Ps[wrow + gid + 8][ks * 8 + tig]);
                pa[ks][2] = __float_as_uint(Ps[wrow + gid][ks * 8 + tig + 4]);
                pa[ks][3] = __float_as_uint(Ps[wrow + gid + 8][ks * 8 + tig + 4]);
            }
#pragma unroll
            for (int nt = 0; nt < 8; nt++) {
#pragma unroll
                for (int ks = 0; ks < 4; ks++) {
                    uint32_t b[2];
                    b[0] = __float_as_uint(Vs[ks * 8 + tig][nt * 8 + gid]);
                    b[1] = __float_as_uint(Vs[ks * 8 + tig + 4][nt * 8 + gid]);
                    mma_tf32(o[nt], pa[ks], b);
                }
            }
        }
        __syncthreads();   // Ks/Vs consumed; safe to overwrite next tile
    }

    // --- normalize + write ctx [B,S,H] ---
    const int b  = bh >> 4;
    const int nh = bh & 15;
    const float inv0 = 1.0f / l0;
    const float inv1 = 1.0f / l1;
    float* orow0 = ctx + (size_t)(b * S_ + r0g) * H_ + nh * HD_;
    float* orow1 = ctx + (size_t)(b * S_ + r1g) * H_ + nh * HD_;
#pragma unroll
    for (int nt = 0; nt < 8; nt++) {
        int col = nt * 8 + tig * 2;
        *(float2*)&orow0[col] = make_float2(o[nt][0] * inv0, o[nt][1] * inv0);
        *(float2*)&orow1[col] = make_float2(o[nt][2] * inv1, o[nt][3] * inv1);
    }
}

// ---------------------------------------------------------------------------
extern "C" void kernel_launch(void* const* d_in, const int* in_sizes, int n_in,
                              void* d_out, int out_size)
{
    const float* hs = (const float*)d_in[0];
    const float* Wa = (const float*)d_in[1];
    const float* ba = (const float*)d_in[2];
    const float* Wp = (const float*)d_in[3];
    const float* bp = (const float*)d_in[4];
    const float* qg = (const float*)d_in[5];
    const float* qb = (const float*)d_in[6];
    const float* kg = (const float*)d_in[7];
    const float* kb = (const float*)d_in[8];
    float* out = (float*)d_out;

    float *qkv, *qh, *kh, *vh, *ctx;
    cudaGetSymbolAddress((void**)&qkv, g_qkv);
    cudaGetSymbolAddress((void**)&qh,  g_qh);
    cudaGetSymbolAddress((void**)&kh,  g_kh);
    cudaGetSymbolAddress((void**)&vh,  g_vh);
    cudaGetSymbolAddress((void**)&ctx, g_ctx);

    // 1) QKV GEMM: [4096,1024] @ [1024,3072] + bias (tf32 tensor cores)
    gemm_tf32<<<dim3(3 * H_ / 128, MROWS_ / 128), 256>>>(hs, Wa, ba, qkv,
                                                         MROWS_, 3 * H_, H_);

    // 2) split + QK layernorm
    {
        int warps = 3 * LN_ROWS_;
        int blocks = (warps * 32 + 255) / 256;
        qkv_split_ln<<<blocks, 256>>>(qkv, qg, qb, kg, kb, qh, kh, vh);
    }

    // 3) causal flash attention (tf32 tensor cores)
    flash_attn_tc<<<dim3(S_ / 64, B_ * NH_), 128>>>(qh, kh, vh, ctx);

    // 4) output projection: [4096,1024] @ [1024,1024] + bias
    gemm_tf32<<<dim3(H_ / 128, MROWS_ / 128), 256>>>(ctx, Wp, bp, out,
                                                     MROWS_, H_, H_);
}

// round 4
// speedup vs baseline: 2.7681x; 1.2913x over previous
#include <cuda_runtime.h>
#include <cuda_bf16.h>
#include <math_constants.h>
#include <cstdint>

// Problem constants
#define B_  2
#define S_  2048
#define H_  1024
#define NH_ 16
#define HD_ 64
#define MROWS_ (B_ * S_)          // 4096
#define LN_ROWS_ (B_ * S_ * NH_)  // 65536

// Scratch (device globals — allocation-free rule)
__device__ float g_qkv[(size_t)MROWS_ * 3 * H_];  // [4096, 3072]
__device__ float g_qh [(size_t)MROWS_ * H_];      // [B*NH, S, HD]
__device__ float g_kh [(size_t)MROWS_ * H_];
__device__ float g_vh [(size_t)MROWS_ * H_];
__device__ float g_ctx[(size_t)MROWS_ * H_];      // [B, S, H]

// ---------------------------------------------------------------------------
// tf32 helpers
// ---------------------------------------------------------------------------
__device__ __forceinline__ float tf32r(float x) {
    float y;
    asm("cvt.rna.tf32.f32 %0, %1;" : "=f"(y) : "f"(x));
    return y;
}

__device__ __forceinline__ void mma_tf32(float c[4], const uint32_t a[4],
                                         const uint32_t b[2]) {
    asm volatile(
        "mma.sync.aligned.m16n8k8.row.col.f32.tf32.tf32.f32 "
        "{%0,%1,%2,%3}, {%4,%5,%6,%7}, {%8,%9}, {%0,%1,%2,%3};"
        : "+f"(c[0]), "+f"(c[1]), "+f"(c[2]), "+f"(c[3])
        : "r"(a[0]), "r"(a[1]), "r"(a[2]), "r"(a[3]), "r"(b[0]), "r"(b[1]));
}

// ---------------------------------------------------------------------------
// TF32 tensor-core GEMM: C[M,N] = A[M,K] @ B[K,N] + bias[N]
// 128x128 tile, BK=16 double-buffered. 8 warps of 64x32 (4x4 m16n8k8).
// Smem layouts chosen for conflict-free FRAGMENT LOADS:
//   As2[m][k]  row stride 20  -> A-frag bank = (gid*20+tig) mod 32, distinct
//   Bs2[k][n]  row stride 136 -> B-frag bank = (tig*8+gid), distinct
// ---------------------------------------------------------------------------
#define AP 20
#define BP 136

__global__ __launch_bounds__(256, 2) void gemm_tf32(
    const float* __restrict__ A, const float* __restrict__ Bm,
    const float* __restrict__ bias, float* __restrict__ C,
    int M, int N, int K)
{
    __shared__ float As2[2][128][AP];
    __shared__ float Bs2[2][16][BP];

    const int tid  = threadIdx.x;
    const int lane = tid & 31;
    const int warp = tid >> 5;
    const int wm = (warp & 1) * 64;
    const int wn = (warp >> 1) * 32;
    const int gid = lane >> 2;
    const int tig = lane & 3;
    const int brow = blockIdx.y * 128;
    const int bcol = blockIdx.x * 128;

    const int aRow = tid >> 2;        // 0..63 (+64)
    const int aCol = (tid & 3) * 4;   // 0,4,8,12
    const int bRow = tid >> 5;        // 0..7 (+8)
    const int bCol = (tid & 31) * 4;  // 0..124

    const float* Aptr  = A + (size_t)(brow + aRow) * K + aCol;
    const float* Aptr2 = Aptr + (size_t)64 * K;
    const float* Bptr  = Bm + (size_t)bRow * N + bcol + bCol;
    const float* Bptr2 = Bptr + (size_t)8 * N;

    float c[4][4][4];
#pragma unroll
    for (int i = 0; i < 4; i++)
#pragma unroll
        for (int j = 0; j < 4; j++)
#pragma unroll
            for (int r = 0; r < 4; r++) c[i][j][r] = 0.f;

    float4 av0, av1, bv0, bv1;

    // prologue
    av0 = *(const float4*)(Aptr);
    av1 = *(const float4*)(Aptr2);
    bv0 = *(const float4*)(Bptr);
    bv1 = *(const float4*)(Bptr2);
    {
        float4 a0 = make_float4(tf32r(av0.x), tf32r(av0.y), tf32r(av0.z), tf32r(av0.w));
        float4 a1 = make_float4(tf32r(av1.x), tf32r(av1.y), tf32r(av1.z), tf32r(av1.w));
        *(float4*)&As2[0][aRow][aCol]      = a0;
        *(float4*)&As2[0][aRow + 64][aCol] = a1;
        float4 t0 = make_float4(tf32r(bv0.x), tf32r(bv0.y), tf32r(bv0.z), tf32r(bv0.w));
        float4 t1 = make_float4(tf32r(bv1.x), tf32r(bv1.y), tf32r(bv1.z), tf32r(bv1.w));
        *(float4*)&Bs2[0][bRow][bCol]     = t0;
        *(float4*)&Bs2[0][bRow + 8][bCol] = t1;
    }
    __syncthreads();

    const int iters = K / 16;
    for (int t = 0; t < iters; t++) {
        const int buf = t & 1;
        if (t + 1 < iters) {
            const int k0 = (t + 1) * 16;
            av0 = *(const float4*)(Aptr + k0);
            av1 = *(const float4*)(Aptr2 + k0);
            bv0 = *(const float4*)(Bptr + (size_t)k0 * N);
            bv1 = *(const float4*)(Bptr2 + (size_t)k0 * N);
        }

#pragma unroll
        for (int ks = 0; ks < 2; ks++) {
            const int k0 = ks * 8;
            uint32_t af[4][4], bf[4][2];
#pragma unroll
            for (int mt = 0; mt < 4; mt++) {
                const int r = wm + mt * 16 + gid;
                af[mt][0] = __float_as_uint(As2[buf][r][k0 + tig]);
                af[mt][1] = __float_as_uint(As2[buf][r + 8][k0 + tig]);
                af[mt][2] = __float_as_uint(As2[buf][r][k0 + tig + 4]);
                af[mt][3] = __float_as_uint(As2[buf][r + 8][k0 + tig + 4]);
            }
#pragma unroll
            for (int nt = 0; nt < 4; nt++) {
                const int ncol = wn + nt * 8 + gid;
                bf[nt][0] = __float_as_uint(Bs2[buf][k0 + tig][ncol]);
                bf[nt][1] = __float_as_uint(Bs2[buf][k0 + tig + 4][ncol]);
            }
#pragma unroll
            for (int mt = 0; mt < 4; mt++)
#pragma unroll
                for (int nt = 0; nt < 4; nt++)
                    mma_tf32(c[mt][nt], af[mt], bf[nt]);
        }

        if (t + 1 < iters) {
            const int nb = (t + 1) & 1;
            float4 a0 = make_float4(tf32r(av0.x), tf32r(av0.y), tf32r(av0.z), tf32r(av0.w));
            float4 a1 = make_float4(tf32r(av1.x), tf32r(av1.y), tf32r(av1.z), tf32r(av1.w));
            *(float4*)&As2[nb][aRow][aCol]      = a0;
            *(float4*)&As2[nb][aRow + 64][aCol] = a1;
            float4 t0 = make_float4(tf32r(bv0.x), tf32r(bv0.y), tf32r(bv0.z), tf32r(bv0.w));
            float4 t1 = make_float4(tf32r(bv1.x), tf32r(bv1.y), tf32r(bv1.z), tf32r(bv1.w));
            *(float4*)&Bs2[nb][bRow][bCol]     = t0;
            *(float4*)&Bs2[nb][bRow + 8][bCol] = t1;
            __syncthreads();
        }
    }

    // epilogue: bias add + store
#pragma unroll
    for (int mt = 0; mt < 4; mt++) {
        const int row = brow + wm + mt * 16 + gid;
#pragma unroll
        for (int nt = 0; nt < 4; nt++) {
            const int col = bcol + wn + nt * 8 + tig * 2;
            const float b0 = bias[col], b1 = bias[col + 1];
            float2 o0 = make_float2(c[mt][nt][0] + b0, c[mt][nt][1] + b1);
            float2 o1 = make_float2(c[mt][nt][2] + b0, c[mt][nt][3] + b1);
            *(float2*)&C[(size_t)row * N + col]       = o0;
            *(float2*)&C[(size_t)(row + 8) * N + col] = o1;
        }
    }
}

// ---------------------------------------------------------------------------
// Split QKV + per-head LayerNorm on Q,K (HD=64), plain copy for V.
// ---------------------------------------------------------------------------
__global__ __launch_bounds__(256) void qkv_split_ln(
    const float* __restrict__ qkv,
    const float* __restrict__ qg, const float* __restrict__ qb,
    const float* __restrict__ kg, const float* __restrict__ kb,
    float* __restrict__ qh, float* __restrict__ kh, float* __restrict__ vh)
{
    int w = (blockIdx.x * blockDim.x + threadIdx.x) >> 5;
    int lane = threadIdx.x & 31;
    int t = w / LN_ROWS_;
    int row = w - t * LN_ROWS_;
    if (t >= 3) return;

    int b = row / (S_ * NH_);
    int rem = row - b * (S_ * NH_);
    int s = rem / NH_;
    int n = rem - s * NH_;

    const float* src = qkv + (size_t)(b * S_ + s) * (3 * H_) + t * H_ + n * HD_;
    float* dst = (t == 0 ? qh : (t == 1 ? kh : vh)) +
                 ((size_t)(b * NH_ + n) * S_ + s) * HD_;

    float x0 = src[lane];
    float x1 = src[lane + 32];
    if (t == 2) { dst[lane] = x0; dst[lane + 32] = x1; return; }

    float s1 = x0 + x1;
    float s2 = x0 * x0 + x1 * x1;
#pragma unroll
    for (int o = 16; o > 0; o >>= 1) {
        s1 += __shfl_xor_sync(0xffffffffu, s1, o);
        s2 += __shfl_xor_sync(0xffffffffu, s2, o);
    }
    float mu  = s1 * (1.0f / HD_);
    float var = s2 * (1.0f / HD_) - mu * mu;
    float inv = rsqrtf(var + 1e-5f);

    const float* g  = (t == 0) ? qg : kg;
    const float* be = (t == 0) ? qb : kb;
    dst[lane]      = (x0 - mu) * inv * g[lane]      + be[lane];
    dst[lane + 32] = (x1 - mu) * inv * g[lane + 32] + be[lane + 32];
}

// ---------------------------------------------------------------------------
// Causal flash attention, TF32 tensor cores.
// ---------------------------------------------------------------------------
__global__ __launch_bounds__(128, 3) void flash_attn_tc(
    const float* __restrict__ qh, const float* __restrict__ kh,
    const float* __restrict__ vh, float* __restrict__ ctx)
{
    __shared__ float Ks[32][68];
    __shared__ float Vs[32][72];
    __shared__ float Ps[64][36];

    const int bh  = blockIdx.y;
    const int qt  = blockIdx.x;
    const int tid = threadIdx.x;
    const int lane = tid & 31;
    const int w    = tid >> 5;
    const int gid  = lane >> 2;
    const int tig  = lane & 3;
    const int qbase = qt * 64;
    const int wrow  = w * 16;

    const float* Q  = qh + (size_t)bh * S_ * HD_ + (size_t)qbase * HD_;
    const float* Kp = kh + (size_t)bh * S_ * HD_;
    const float* Vp = vh + (size_t)bh * S_ * HD_;

    uint32_t qa[8][4];
#pragma unroll
    for (int h = 0; h < 2; h++) {
        for (int i = tid; i < 64 * 8; i += 128) {
            int r = i >> 3, c4 = (i & 7) * 4;
            float4 v = *(const float4*)&Q[r * HD_ + h * 32 + c4];
            Ps[r][c4 + 0] = tf32r(v.x);
            Ps[r][c4 + 1] = tf32r(v.y);
            Ps[r][c4 + 2] = tf32r(v.z);
            Ps[r][c4 + 3] = tf32r(v.w);
        }
        __syncthreads();
#pragma unroll
        for (int ks = 0; ks < 4; ks++) {
            qa[h * 4 + ks][0] = __float_as_uint(Ps[wrow + gid][ks * 8 + tig]);
            qa[h * 4 + ks][1] = __float_as_uint(Ps[wrow + gid + 8][ks * 8 + tig]);
            qa[h * 4 + ks][2] = __float_as_uint(Ps[wrow + gid][ks * 8 + tig + 4]);
            qa[h * 4 + ks][3] = __float_as_uint(Ps[wrow + gid + 8][ks * 8 + tig + 4]);
        }
        __syncthreads();
    }

    float o[8][4];
#pragma unroll
    for (int i = 0; i < 8; i++)
#pragma unroll
        for (int j = 0; j < 4; j++) o[i][j] = 0.f;
    float m0 = -CUDART_INF_F, m1 = -CUDART_INF_F;
    float l0 = 0.f, l1 = 0.f;

    const int r0g = qbase + wrow + gid;
    const int r1g = r0g + 8;
    const int rmaxw = qbase + wrow + 15;
    const int nkt = (qt + 1) * 2;
    const float scl = 0.125f;

    for (int kt = 0; kt < nkt; kt++) {
        const int kbase = kt * 32;
        for (int i = tid; i < 32 * 16; i += 128) {
            int r = i >> 4, c4 = (i & 15) * 4;
            const float* kp = &Kp[(size_t)(kbase + r) * HD_ + c4];
            float4 kv = *(const float4*)kp;
            Ks[r][c4 + 0] = tf32r(kv.x); Ks[r][c4 + 1] = tf32r(kv.y);
            Ks[r][c4 + 2] = tf32r(kv.z); Ks[r][c4 + 3] = tf32r(kv.w);
            const float* vp = &Vp[(size_t)(kbase + r) * HD_ + c4];
            float4 vv = *(const float4*)vp;
            Vs[r][c4 + 0] = tf32r(vv.x); Vs[r][c4 + 1] = tf32r(vv.y);
            Vs[r][c4 + 2] = tf32r(vv.z); Vs[r][c4 + 3] = tf32r(vv.w);
        }
        __syncthreads();

        if (kbase <= rmaxw) {
            float s[4][4];
#pragma unroll
            for (int nt = 0; nt < 4; nt++)
#pragma unroll
                for (int j = 0; j < 4; j++) s[nt][j] = 0.f;
#pragma unroll
            for (int nt = 0; nt < 4; nt++) {
#pragma unroll
                for (int ks = 0; ks < 8; ks++) {
                    uint32_t b[2];
                    b[0] = __float_as_uint(Ks[nt * 8 + gid][ks * 8 + tig]);
                    b[1] = __float_as_uint(Ks[nt * 8 + gid][ks * 8 + tig + 4]);
                    mma_tf32(s[nt], qa[ks], b);
                }
            }

            if (kbase + 31 <= qbase + wrow) {
#pragma unroll
                for (int nt = 0; nt < 4; nt++)
#pragma unroll
                    for (int j = 0; j < 4; j++) s[nt][j] *= scl;
            } else {
#pragma unroll
                for (int nt = 0; nt < 4; nt++) {
                    int c0 = kbase + nt * 8 + tig * 2;
                    s[nt][0] = (c0     <= r0g) ? s[nt][0] * scl : -CUDART_INF_F;
                    s[nt][1] = (c0 + 1 <= r0g) ? s[nt][1] * scl : -CUDART_INF_F;
                    s[nt][2] = (c0     <= r1g) ? s[nt][2] * scl : -CUDART_INF_F;
                    s[nt][3] = (c0 + 1 <= r1g) ? s[nt][3] * scl : -CUDART_INF_F;
                }
            }

            float mt0 = fmaxf(fmaxf(s[0][0], s[0][1]), fmaxf(s[1][0], s[1][1]));
            mt0 = fmaxf(mt0, fmaxf(fmaxf(s[2][0], s[2][1]), fmaxf(s[3][0], s[3][1])));
            float mt1 = fmaxf(fmaxf(s[0][2], s[0][3]), fmaxf(s[1][2], s[1][3]));
            mt1 = fmaxf(mt1, fmaxf(fmaxf(s[2][2], s[2][3]), fmaxf(s[3][2], s[3][3])));
            mt0 = fmaxf(mt0, __shfl_xor_sync(0xffffffffu, mt0, 1));
            mt0 = fmaxf(mt0, __shfl_xor_sync(0xffffffffu, mt0, 2));
            mt1 = fmaxf(mt1, __shfl_xor_sync(0xffffffffu, mt1, 1));
            mt1 = fmaxf(mt1, __shfl_xor_sync(0xffffffffu, mt1, 2));

            float mn0 = fmaxf(m0, mt0), mn1 = fmaxf(m1, mt1);
            float a0 = __expf(m0 - mn0), a1 = __expf(m1 - mn1);
            m0 = mn0; m1 = mn1;

            float ps0 = 0.f, ps1 = 0.f;
#pragma unroll
            for (int nt = 0; nt < 4; nt++) {
                float p0 = tf32r(__expf(s[nt][0] - mn0));
                float p1 = tf32r(__expf(s[nt][1] - mn0));
                float p2 = tf32r(__expf(s[nt][2] - mn1));
                float p3 = tf32r(__expf(s[nt][3] - mn1));
                ps0 += p0 + p1;
                ps1 += p2 + p3;
                Ps[wrow + gid][nt * 8 + tig * 2 + 0]     = p0;
                Ps[wrow + gid][nt * 8 + tig * 2 + 1]     = p1;
                Ps[wrow + gid + 8][nt * 8 + tig * 2 + 0] = p2;
                Ps[wrow + gid + 8][nt * 8 + tig * 2 + 1] = p3;
            }
            ps0 += __shfl_xor_sync(0xffffffffu, ps0, 1);
            ps0 += __shfl_xor_sync(0xffffffffu, ps0, 2);
            ps1 += __shfl_xor_sync(0xffffffffu, ps1, 1);
            ps1 += __shfl_xor_sync(0xffffffffu, ps1, 2);
            l0 = l0 * a0 + ps0;
            l1 = l1 * a1 + ps1;

#pragma unroll
            for (int nt = 0; nt < 8; nt++) {
                o[nt][0] *= a0; o[nt][1] *= a0;
                o[nt][2] *= a1; o[nt][3] *= a1;
            }

            uint32_t pa[4][4];
#pragma unroll
            for (int ks = 0; ks < 4; ks++) {
                pa[ks][0] = __float_as_uint(Ps[wrow + gid][ks * 8 + tig]);
                pa[ks][1] = __float_as_uint(Ps[wrow + gid + 8][ks * 8 + tig]);
                pa[ks][2] = __float_as_uint(Ps[wrow + gid][ks * 8 + tig + 4]);
                pa[ks][3] = __float_as_uint(Ps[wrow + gid + 8][ks * 8 + tig + 4]);
            }
#pragma unroll
            for (int nt = 0; nt < 8; nt++) {
#pragma unroll
                for (int ks = 0; ks < 4; ks++) {
                    uint32_t b[2];
                    b[0] = __float_as_uint(Vs[ks * 8 + tig][nt * 8 + gid]);
                    b[1] = __float_as_uint(Vs[ks * 8 + tig + 4][nt * 8 + gid]);
                    mma_tf32(o[nt], pa[ks], b);
                }
            }
        }
        __syncthreads();
    }

    const int b  = bh >> 4;
    const int nh = bh & 15;
    const float inv0 = 1.0f / l0;
    const float inv1 = 1.0f / l1;
    float* orow0 = ctx + (size_t)(b * S_ + r0g) * H_ + nh * HD_;
    float* orow1 = ctx + (size_t)(b * S_ + r1g) * H_ + nh * HD_;
#pragma unroll
    for (int nt = 0; nt < 8; nt++) {
        int col = nt * 8 + tig * 2;
        *(float2*)&orow0[col] = make_float2(o[nt][0] * inv0, o[nt][1] * inv0);
        *(float2*)&orow1[col] = make_float2(o[nt][2] * inv1, o[nt][3] * inv1);
    }
}

// ---------------------------------------------------------------------------
extern "C" void kernel_launch(void* const* d_in, const int* in_sizes, int n_in,
                              void* d_out, int out_size)
{
    const float* hs = (const float*)d_in[0];
    const float* Wa = (const float*)d_in[1];
    const float* ba = (const float*)d_in[2];
    const float* Wp = (const float*)d_in[3];
    const float* bp = (const float*)d_in[4];
    const float* qg = (const float*)d_in[5];
    const float* qb = (const float*)d_in[6];
    const float* kg = (const float*)d_in[7];
    const float* kb = (const float*)d_in[8];
    float* out = (float*)d_out;

    float *qkv, *qh, *kh, *vh, *ctx;
    cudaGetSymbolAddress((void**)&qkv, g_qkv);
    cudaGetSymbolAddress((void**)&qh,  g_qh);
    cudaGetSymbolAddress((void**)&kh,  g_kh);
    cudaGetSymbolAddress((void**)&vh,  g_vh);
    cudaGetSymbolAddress((void**)&ctx, g_ctx);

    // 1) QKV GEMM: [4096,1024] @ [1024,3072] + bias (tf32 tensor cores)
    gemm_tf32<<<dim3(3 * H_ / 128, MROWS_ / 128), 256>>>(hs, Wa, ba, qkv,
                                                         MROWS_, 3 * H_, H_);

    // 2) split + QK layernorm
    {
        int warps = 3 * LN_ROWS_;
        int blocks = (warps * 32 + 255) / 256;
        qkv_split_ln<<<blocks, 256>>>(qkv, qg, qb, kg, kb, qh, kh, vh);
    }

    // 3) causal flash attention (tf32 tensor cores)
    flash_attn_tc<<<dim3(S_ / 64, B_ * NH_), 128>>>(qh, kh, vh, ctx);

    // 4) output projection: [4096,1024] @ [1024,1024] + bias
    gemm_tf32<<<dim3(H_ / 128, MROWS_ / 128), 256>>>(ctx, Wp, bp, out,
                                                     MROWS_, H_, H_);
}